// round 14
// baseline (speedup 1.0000x reference)
#include <cuda_runtime.h>
#include <stdint.h>

#define NB 256
#define NE 512
#define NC 256
#define NAR 1024
#define NH 256
#define NK 32
#define NSTEPS 64

typedef unsigned long long ull;

// ---------------- static device scratch ----------------
__device__ float g_xpart[8 * NB * NH];
__device__ float g_WpW1[NK * NH];
__device__ float g_bpW1[NH];
__device__ float g_kpT[(size_t)NB * NE * NK];          // 16 MB, layout [b][e][h]
__device__ float g_func[NB * NH];
__device__ float g_gumbel[(size_t)NB * NSTEPS * NE];   // 32 MB, layout [b][s][e]
__device__ int   g_action[NB];

#define OFF_UNITS ((size_t)NB * NSTEPS * NE)
#define OFF_AR    (OFF_UNITS + (size_t)NB * NSTEPS)

struct SubKeys { unsigned int a[64]; unsigned int b[64]; };

// ---------------- f32x2 packed helpers ----------------
__device__ __forceinline__ void ffma2(ull &d, ull a, ull b) {
  asm("fma.rn.f32x2 %0, %1, %2, %3;" : "=l"(d) : "l"(a), "l"(b), "l"(d));
}
__device__ __forceinline__ ull fadd2(ull a, ull b) {
  ull r; asm("add.rn.f32x2 %0, %1, %2;" : "=l"(r) : "l"(a), "l"(b)); return r;
}
__device__ __forceinline__ ull dup2(float x) {
  ull r; asm("mov.b64 %0, {%1, %1};" : "=l"(r) : "f"(x)); return r;
}
__device__ __forceinline__ ull pack2(float x, float y) {
  ull r; asm("mov.b64 %0, {%1, %2};" : "=l"(r) : "f"(x), "f"(y)); return r;
}
__device__ __forceinline__ float2 unpack2(ull v) {
  float2 r; asm("mov.b64 {%0, %1}, %2;" : "=f"(r.x), "=f"(r.y) : "l"(v)); return r;
}

// ---------------- Threefry-2x32 (20 rounds), device ----------------
__device__ __forceinline__ void tf2x32(uint32_t k0, uint32_t k1,
                                       uint32_t x0, uint32_t x1,
                                       uint32_t &o0, uint32_t &o1) {
  uint32_t ks2 = k0 ^ k1 ^ 0x1BD11BDAu;
  x0 += k0; x1 += k1;
#define RND(r) { x0 += x1; x1 = __funnelshift_l(x1, x1, (r)); x1 ^= x0; }
  RND(13) RND(15) RND(26) RND(6)   x0 += k1;  x1 += ks2 + 1u;
  RND(17) RND(29) RND(16) RND(24)  x0 += ks2; x1 += k0  + 2u;
  RND(13) RND(15) RND(26) RND(6)   x0 += k0;  x1 += k1  + 3u;
  RND(17) RND(29) RND(16) RND(24)  x0 += k1;  x1 += ks2 + 4u;
  RND(13) RND(15) RND(26) RND(6)   x0 += ks2; x1 += k0  + 5u;
#undef RND
  o0 = x0; o1 = x1;
}

__device__ __forceinline__ float gumbelize(uint32_t bits) {
  float f = __uint_as_float((bits >> 9) | 0x3f800000u) - 1.0f;
  f = fmaxf(f, 1e-20f);
  return -__logf(-__logf(f));
}

__device__ __forceinline__ unsigned fenc(float f) {
  unsigned u = __float_as_uint(f);
  return (u & 0x80000000u) ? ~u : (u | 0x80000000u);
}

// ---------------- gumbel kernel (side stream) ----------------
__global__ void gumbel_kernel(SubKeys sk) {
  int v0 = (blockIdx.x * 256 + threadIdx.x) * 4;
  int b = v0 >> 15;
  int rem = v0 & 32767;
  int s = rem >> 9;
  int e = rem & 511;
  int j = b * 512 + e;
  uint32_t k0 = sk.a[s], k1 = sk.b[s];
  float4 r;
  uint32_t o0, o1;
  tf2x32(k0, k1, 0u, (uint32_t)j,     o0, o1); r.x = gumbelize(o0 ^ o1);
  tf2x32(k0, k1, 0u, (uint32_t)(j+1), o0, o1); r.y = gumbelize(o0 ^ o1);
  tf2x32(k0, k1, 0u, (uint32_t)(j+2), o0, o1); r.z = gumbelize(o0 ^ o1);
  tf2x32(k0, k1, 0u, (uint32_t)(j+3), o0, o1); r.w = gumbelize(o0 ^ o1);
  *(float4*)(g_gumbel + (size_t)v0) = r;
}

// ---------------- side precompute: xpart gemm (256) + wpw1 (33) ----------------
#define GEMM_BLKS 256
#define WPW1_BLKS 33
__global__ void precompute_side_kernel(const float* __restrict__ Wp, const float* __restrict__ bp,
                                       const float* __restrict__ W1, const float* __restrict__ ar0,
                                       const float* __restrict__ b1) {
  __shared__ __align__(16) float psm[1616];
  int blk = blockIdx.x;
  int t = threadIdx.x;

  if (blk < GEMM_BLKS) {
    int bx = blk & 3, by = (blk >> 2) & 7, bz = blk >> 5;
    float* As = psm;
    float* Bs = psm + 528;
    int bm = by * 32, bn = bx * 64, k0 = bz * 128;
    int ty = t >> 4, tx = t & 15;
    float acc[2][4] = {{0.f,0.f,0.f,0.f},{0.f,0.f,0.f,0.f}};
    for (int kc = 0; kc < 128; kc += 16) {
      {
        int m = t >> 3;
        int kk = (t & 7) * 2;
        const float* p = ar0 + (size_t)(bm + m) * NAR + (k0 + kc + kk);
        As[kk * 33 + m] = p[0];
        As[(kk + 1) * 33 + m] = p[1];
      }
      {
        int kk = t >> 4;
        int j = (t & 15) * 4;
        const float* p = W1 + (size_t)(k0 + kc + kk) * NH + bn + j;
        Bs[kk * 68 + j] = p[0]; Bs[kk * 68 + j+1] = p[1]; Bs[kk * 68 + j+2] = p[2]; Bs[kk * 68 + j+3] = p[3];
      }
      __syncthreads();
      #pragma unroll
      for (int k = 0; k < 16; k++) {
        float a0 = As[k * 33 + ty * 2], a1 = As[k * 33 + ty * 2 + 1];
        float4 bv = *reinterpret_cast<const float4*>(&Bs[k * 68 + tx * 4]);
        acc[0][0] += a0 * bv.x; acc[0][1] += a0 * bv.y; acc[0][2] += a0 * bv.z; acc[0][3] += a0 * bv.w;
        acc[1][0] += a1 * bv.x; acc[1][1] += a1 * bv.y; acc[1][2] += a1 * bv.z; acc[1][3] += a1 * bv.w;
      }
      __syncthreads();
    }
    float* xp = g_xpart + (size_t)bz * (NB * NH);
    #pragma unroll
    for (int im = 0; im < 2; im++) {
      int row = bm + ty * 2 + im;
      float* o = xp + (size_t)row * NH + bn + tx * 4;
      float bb0 = (bz == 0) ? b1[bn + tx * 4]     : 0.f;
      float bb1 = (bz == 0) ? b1[bn + tx * 4 + 1] : 0.f;
      float bb2 = (bz == 0) ? b1[bn + tx * 4 + 2] : 0.f;
      float bb3 = (bz == 0) ? b1[bn + tx * 4 + 3] : 0.f;
      o[0] = acc[im][0] + bb0; o[1] = acc[im][1] + bb1;
      o[2] = acc[im][2] + bb2; o[3] = acc[im][3] + bb3;
    }
  } else {
    float* s_row = psm;
    int i = blk - GEMM_BLKS;
    for (int k = t; k < NAR; k += 256)
      s_row[k] = (i < NK) ? Wp[(size_t)i * NAR + k] : bp[k];
    __syncthreads();
    float a0 = 0.f, a1 = 0.f, a2 = 0.f, a3 = 0.f;
    for (int k = 0; k < NAR; k += 4) {
      a0 += s_row[k]     * W1[(size_t)k * NH + t];
      a1 += s_row[k + 1] * W1[(size_t)(k + 1) * NH + t];
      a2 += s_row[k + 2] * W1[(size_t)(k + 2) * NH + t];
      a3 += s_row[k + 3] * W1[(size_t)(k + 3) * NH + t];
    }
    float acc = (a0 + a1) + (a2 + a3);
    if (i < NK) g_WpW1[i * NH + t] = acc; else g_bpW1[t] = acc;
  }
}

// ---------------- main precompute: keyproj (512) + action (1) + func (256) ----------------
#define KP_BLKS   512
#define FUNC_BLKS 256
__global__ void precompute_main_kernel(const int* __restrict__ action_raw,
                                       const float* __restrict__ emb, const float* __restrict__ Wk,
                                       const float* __restrict__ bk, const float* __restrict__ Wf,
                                       const float* __restrict__ bf, const float* __restrict__ table) {
  __shared__ __align__(16) float psm[8192];
  int blk = blockIdx.x;
  int t = threadIdx.x;

  if (blk < KP_BLKS) {
    int b = blk >> 1, pass = blk & 1;
    for (int i = t; i < NC * NK; i += 256) psm[i] = Wk[i];
    __syncthreads();
    int hg = t & 3, rquad = t >> 2;
    int h0 = hg * 8;
    int r0 = pass * 256 + rquad * 4;
    ull bkp[4];
    #pragma unroll
    for (int j = 0; j < 4; j++) bkp[j] = pack2(bk[h0 + 2*j], bk[h0 + 2*j + 1]);
    ull acc[4][4];
    #pragma unroll
    for (int i = 0; i < 4; i++)
      #pragma unroll
      for (int j = 0; j < 4; j++) acc[i][j] = bkp[j];

    const float* e0p = emb + ((size_t)b * NE + r0) * NC;
    float4 curA0 = __ldcs((const float4*)(e0p));
    float4 curA1 = __ldcs((const float4*)(e0p + NC));
    float4 curA2 = __ldcs((const float4*)(e0p + 2 * NC));
    float4 curA3 = __ldcs((const float4*)(e0p + 3 * NC));
    float4 curB0 = __ldcs((const float4*)(e0p + 4));
    float4 curB1 = __ldcs((const float4*)(e0p + NC + 4));
    float4 curB2 = __ldcs((const float4*)(e0p + 2 * NC + 4));
    float4 curB3 = __ldcs((const float4*)(e0p + 3 * NC + 4));
    for (int c = 0; c < NC; c += 4) {
      float4 e0 = curA0, e1 = curA1, e2 = curA2, e3 = curA3;
      curA0 = curB0; curA1 = curB1; curA2 = curB2; curA3 = curB3;
      if (c + 8 < NC) {
        curB0 = __ldcs((const float4*)(e0p + c + 8));
        curB1 = __ldcs((const float4*)(e0p + NC + c + 8));
        curB2 = __ldcs((const float4*)(e0p + 2 * NC + c + 8));
        curB3 = __ldcs((const float4*)(e0p + 3 * NC + c + 8));
      }
      #pragma unroll
      for (int cc = 0; cc < 4; cc++) {
        const float* wp = psm + (c + cc) * 32 + h0;
        ull w0 = *(const ull*)(wp);
        ull w1 = *(const ull*)(wp + 2);
        ull w2 = *(const ull*)(wp + 4);
        ull w3 = *(const ull*)(wp + 6);
        ull a0 = dup2(((const float*)&e0)[cc]);
        ull a1 = dup2(((const float*)&e1)[cc]);
        ull a2 = dup2(((const float*)&e2)[cc]);
        ull a3 = dup2(((const float*)&e3)[cc]);
        ffma2(acc[0][0], a0, w0); ffma2(acc[0][1], a0, w1); ffma2(acc[0][2], a0, w2); ffma2(acc[0][3], a0, w3);
        ffma2(acc[1][0], a1, w0); ffma2(acc[1][1], a1, w1); ffma2(acc[1][2], a1, w2); ffma2(acc[1][3], a1, w3);
        ffma2(acc[2][0], a2, w0); ffma2(acc[2][1], a2, w1); ffma2(acc[2][2], a2, w2); ffma2(acc[2][3], a2, w3);
        ffma2(acc[3][0], a3, w0); ffma2(acc[3][1], a3, w1); ffma2(acc[3][2], a3, w2); ffma2(acc[3][3], a3, w3);
      }
    }
    float* kpb = g_kpT + (size_t)b * (NE * NK);
    #pragma unroll
    for (int i = 0; i < 4; i++)
      #pragma unroll
      for (int j = 0; j < 4; j++)
        *(ull*)(kpb + (size_t)(r0 + i) * NK + h0 + 2 * j) = acc[i][j];
  } else if (blk == KP_BLKS) {
    int odd = (t < 128) ? action_raw[2 * t + 1] : 0;
    int any = __syncthreads_or(odd != 0);
    g_action[t] = any ? action_raw[t] : action_raw[2 * t];
  } else {
    int b = blk - (KP_BLKS + 1);
    int odd = (t < 128) ? action_raw[2 * t + 1] : 0;
    int any = __syncthreads_or(odd != 0);
    int a = any ? action_raw[b] : action_raw[2 * b];
    psm[t] = table[(size_t)a * 256 + t];
    __syncthreads();
    float a0 = 0.f, a1 = 0.f;
    #pragma unroll 4
    for (int k = 0; k < 256; k += 2) {
      a0 = fmaf(psm[k],     Wf[(size_t)k * 256 + t], a0);
      a1 = fmaf(psm[k + 1], Wf[(size_t)(k + 1) * 256 + t], a1);
    }
    g_func[b * 256 + t] = fmaxf(bf[t] + a0 + a1, 0.0f);
  }
}

// ---------------- persistent per-batch kernel (known-good 172us version) ----------------
#define KPT_S    514
#define OFF_KPT  0
#define OFF_WXH  16448
#define OFF_ZR   24704
#define OFF_T    24960
#define OFF_PART 25216
#define OFF_H    25344
#define OFF_HD   25376
#define OFF_RED  25440
#define OFF_KEY  25456
#define OFF_SUM  25472
#define SMEM_FLOATS 25504

__global__ __launch_bounds__(256, 2) void persist_kernel(
    const float* __restrict__ ar0,
    const float* __restrict__ W2, const float* __restrict__ b2,
    const float* __restrict__ Wx, const float* __restrict__ Wh,
    const float* __restrict__ bl, const float* __restrict__ Wp,
    const float* __restrict__ bp,
    const float* __restrict__ selt, float* __restrict__ out)
{
  extern __shared__ float sm[];
  float* s_kpT  = sm + OFF_KPT;
  float* s_Wxh  = sm + OFF_WXH;
  float* s_zred = sm + OFF_ZR;
  float* s_t    = sm + OFF_T;
  float* s_part = sm + OFF_PART;
  float* s_h    = sm + OFF_H;
  ull*   s_hd   = (ull*)(sm + OFF_HD);
  float* s_red  = sm + OFF_RED;
  ull*   s_key  = (ull*)(sm + OFF_KEY);
  float* s_sum  = sm + OFF_SUM;

  int b = blockIdx.x, t = threadIdx.x;
  int lane = t & 31, wid = t >> 5;

  float sel = selt[g_action[b]];

  // ======== prologue ========
  {
    const float* kpg = g_kpT + (size_t)b * (NE * NK);
    #pragma unroll
    for (int i = t * 4; i < NE * NK; i += 1024) {
      float4 v = *(const float4*)(kpg + i);
      int e = i >> 5, h = i & 31;
      s_kpT[(h + 0) * KPT_S + e] = v.x;
      s_kpT[(h + 1) * KPT_S + e] = v.y;
      s_kpT[(h + 2) * KPT_S + e] = v.z;
      s_kpT[(h + 3) * KPT_S + e] = v.w;
    }
  }
  for (int i = t; i < 4096; i += 256) {
    int k = i >> 7, col = i & 127;
    int g = col >> 5, h = col & 31;
    s_Wxh[k * 258 + h * 8 + g * 2]     = Wx[i];
    s_Wxh[k * 258 + h * 8 + g * 2 + 1] = Wh[i];
  }
  if (t < 32) { s_h[t] = 0.0f; s_hd[t] = 0ull; }

  float func_r = g_func[b * 256 + t];
  float x_r = g_xpart[b * NH + t];      // includes b1 (folded in precompute)
  #pragma unroll
  for (int p = 1; p < 8; p++) x_r += g_xpart[p * (NB * NH) + b * NH + t];

  float wpw1r[32];
  ull w2p[16];
  float csum = 0.f;
  #pragma unroll
  for (int k = 0; k < 32; k++) { wpw1r[k] = g_WpW1[k * NH + t]; csum += wpw1r[k]; }
  #pragma unroll
  for (int j = 0; j < 16; j++)
    w2p[j] = pack2(W2[(size_t)(wid * 32 + 2*j) * 32 + lane],
                   W2[(size_t)(wid * 32 + 2*j + 1) * 32 + lane]);
  float bpw1c = g_bpW1[t] - 0.001953125f * csum;
  float b2r = b2[lane];

  int khalf = wid >> 2;
  int lh = (wid & 3) * 8 + (lane >> 2);
  int lg = lane & 3;
  float blr = bl[lg * 32 + lh];
  float creg = 0.f, sumr = 0.f;
  float m0 = 1.0f, m1 = 1.0f;
  __syncthreads();

  const float* gumbase = g_gumbel + (size_t)b * (NSTEPS * NE) + 2 * t;

  // ======== 64-step loop ========
  for (int s = 0; s < NSTEPS; s++) {
    float2 gpair = *(const float2*)(gumbase + s * NE);
    float hpreg = s_h[lane];

    if (s > 0) {
      ull kk = s_key[0];
      #pragma unroll
      for (int i = 1; i < 8; i++) { ull o = s_key[i]; if (o > kk) kk = o; }
      int id = (int)(0xFFFFFFFFu - (unsigned)(kk & 0xFFFFFFFFull));
      if (id == 2 * t) m0 = 0.0f;
      if (id == 2 * t + 1) m1 = 0.0f;
      const float* kc = s_kpT + id;
      float xv0 = x_r + bpw1c, xv1 = 0.f, xv2 = 0.f, xv3 = 0.f;
      #pragma unroll
      for (int k = 0; k < 32; k += 4) {
        xv0 = fmaf(kc[(k + 0) * KPT_S], wpw1r[k + 0], xv0);
        xv1 = fmaf(kc[(k + 1) * KPT_S], wpw1r[k + 1], xv1);
        xv2 = fmaf(kc[(k + 2) * KPT_S], wpw1r[k + 2], xv2);
        xv3 = fmaf(kc[(k + 3) * KPT_S], wpw1r[k + 3], xv3);
      }
      x_r = (xv0 + xv1) + (xv2 + xv3);
      if (wid == 0) sumr += s_kpT[lane * KPT_S + id] - 0.001953125f;
      if (t == 0) out[OFF_UNITS + (size_t)b * NSTEPS + (s - 1)] = (float)id * sel;
    }
    float tval = fmaxf(func_r + x_r, 0.0f);
    s_t[t] = tval;
    __syncwarp();
    {
      const ull* tp = (const ull*)(s_t + wid * 32);
      ull za = 0ull, zb = 0ull;
      #pragma unroll
      for (int j = 0; j < 16; j += 2) {
        ffma2(za, tp[j], w2p[j]);
        ffma2(zb, tp[j + 1], w2p[j + 1]);
      }
      float2 zv = unpack2(fadd2(za, zb));
      s_zred[t] = zv.x + zv.y;
    }
    __syncthreads();

    float z2l;
    {
      float r0 = s_zred[lane]        + s_zred[32 + lane];
      float r1 = s_zred[64 + lane]   + s_zred[96 + lane];
      float r2 = s_zred[128 + lane]  + s_zred[160 + lane];
      float r3 = s_zred[192 + lane]  + s_zred[224 + lane];
      z2l = b2r + ((r0 + r1) + (r2 + r3));
    }
    {
      float accA = (khalf == 0) ? blr : 0.f, accB = 0.f;
      const float* wbase = s_Wxh + lh * 8 + lg * 2 + khalf * (16 * 258);
      #pragma unroll
      for (int k16 = 0; k16 < 16; k16 += 2) {
        int k = khalf * 16 + k16;
        float z2a = __shfl_sync(0xffffffffu, z2l, k);
        float ha  = __shfl_sync(0xffffffffu, hpreg, k);
        float2 wa = unpack2(*(const ull*)(wbase + k16 * 258));
        accA = fmaf(z2a, wa.x, fmaf(ha, wa.y, accA));
        float z2b = __shfl_sync(0xffffffffu, z2l, k + 1);
        float hb  = __shfl_sync(0xffffffffu, hpreg, k + 1);
        float2 wb = unpack2(*(const ull*)(wbase + (k16 + 1) * 258));
        accB = fmaf(z2b, wb.x, fmaf(hb, wb.y, accB));
      }
      float acc = accA + accB;
      if (khalf == 1) s_part[lh * 4 + lg] = acc;
      __syncthreads();
      if (khalf == 0) {
        acc += s_part[lh * 4 + lg];
        float e2 = __expf((lg == 2) ? (2.f * acc) : (-acc));
        float tg = (lg == 2) ? (1.f - __fdividef(2.f, e2 + 1.f))
                             : __fdividef(1.f, 1.f + e2);
        int base = lane & ~3;
        float iv = __shfl_sync(0xffffffffu, tg, base);
        float fv = __shfl_sync(0xffffffffu, tg, base + 1);
        float gv = __shfl_sync(0xffffffffu, tg, base + 2);
        float ov = __shfl_sync(0xffffffffu, tg, base + 3);
        creg = fv * creg + iv * gv;
        float e2c = __expf(2.f * creg);
        float hv = ov * (1.f - __fdividef(2.f, e2c + 1.f));
        if (lg == 0) { s_h[lh] = hv; s_hd[lh] = dup2(hv); }
      }
    }
    __syncthreads();

    ull a0 = 0ull, a1 = 0ull, a2 = 0ull, a3 = 0ull;
    {
      const float* kb = s_kpT + 2 * t;
      #pragma unroll
      for (int q = 0; q < 8; q++) {
        ffma2(a0, *(const ull*)(kb + (4*q + 0) * KPT_S), s_hd[4*q + 0]);
        ffma2(a1, *(const ull*)(kb + (4*q + 1) * KPT_S), s_hd[4*q + 1]);
        ffma2(a2, *(const ull*)(kb + (4*q + 2) * KPT_S), s_hd[4*q + 2]);
        ffma2(a3, *(const ull*)(kb + (4*q + 3) * KPT_S), s_hd[4*q + 3]);
      }
    }
    float2 yv = unpack2(fadd2(fadd2(a0, a1), fadd2(a2, a3)));
    float y0 = yv.x * m0, y1 = yv.y * m1;
    __stcs((float2*)(out + ((size_t)b * NSTEPS + s) * NE + 2 * t),
           make_float2(y0 * sel, y1 * sel));
    float p0 = __expf(y0), p1 = __expf(y1);
    float ssum = p0 + p1;
    #pragma unroll
    for (int o = 16; o; o >>= 1) ssum += __shfl_xor_sync(0xffffffffu, ssum, o);
    if (lane == 0) s_red[wid] = ssum;
    __syncthreads();

    float S;
    {
      float r0 = s_red[0] + s_red[1], r1 = s_red[2] + s_red[3];
      float r2 = s_red[4] + s_red[5], r3 = s_red[6] + s_red[7];
      S = (r0 + r1) + (r2 + r3);
    }
    float v0 = fmaf(S, gpair.x, p0);
    float v1 = fmaf(S, gpair.y, p1);
    ull kA = ((ull)fenc(v0) << 32) | (ull)(0xFFFFFFFFu - (unsigned)(2 * t));
    ull kB = ((ull)fenc(v1) << 32) | (ull)(0xFFFFFFFFu - (unsigned)(2 * t + 1));
    ull km = (kA > kB) ? kA : kB;
    #pragma unroll
    for (int o = 16; o; o >>= 1) {
      ull other = __shfl_xor_sync(0xffffffffu, km, o);
      if (other > km) km = other;
    }
    if (lane == 0) s_key[wid] = km;
    __syncthreads();
  }

  // ======== final selection ========
  {
    ull kk = s_key[0];
    #pragma unroll
    for (int i = 1; i < 8; i++) { ull o = s_key[i]; if (o > kk) kk = o; }
    int id = (int)(0xFFFFFFFFu - (unsigned)(kk & 0xFFFFFFFFull));
    if (wid == 0) sumr += s_kpT[lane * KPT_S + id] - 0.001953125f;
    if (t == 0) out[OFF_UNITS + (size_t)b * NSTEPS + (NSTEPS - 1)] = (float)id * sel;
  }
  if (wid == 0) s_sum[lane] = sumr;
  __syncthreads();

  // ======== epilogue ========
  for (int j = t; j < NAR; j += 256) {
    float acc0 = ar0[(size_t)b * NAR + j] + 64.0f * bp[j];
    float acc1 = 0.f, acc2 = 0.f, acc3 = 0.f;
    #pragma unroll
    for (int k = 0; k < 32; k += 4) {
      acc0 = fmaf(s_sum[k + 0], Wp[(size_t)(k + 0) * NAR + j], acc0);
      acc1 = fmaf(s_sum[k + 1], Wp[(size_t)(k + 1) * NAR + j], acc1);
      acc2 = fmaf(s_sum[k + 2], Wp[(size_t)(k + 2) * NAR + j], acc2);
      acc3 = fmaf(s_sum[k + 3], Wp[(size_t)(k + 3) * NAR + j], acc3);
    }
    __stcs(out + OFF_AR + (size_t)b * NAR + j, ((acc0 + acc1) + (acc2 + acc3)) * sel);
  }
}

// ---------------- host threefry ----------------
static inline void h_tf2x32(uint32_t k0, uint32_t k1, uint32_t x0, uint32_t x1,
                            uint32_t &o0, uint32_t &o1) {
  uint32_t ks2 = k0 ^ k1 ^ 0x1BD11BDAu;
  x0 += k0; x1 += k1;
#define HRND(r) { x0 += x1; x1 = (x1 << (r)) | (x1 >> (32 - (r))); x1 ^= x0; }
  HRND(13) HRND(15) HRND(26) HRND(6)   x0 += k1;  x1 += ks2 + 1u;
  HRND(17) HRND(29) HRND(16) HRND(24)  x0 += ks2; x1 += k0  + 2u;
  HRND(13) HRND(15) HRND(26) HRND(6)   x0 += k0;  x1 += k1  + 3u;
  HRND(17) HRND(29) HRND(16) HRND(24)  x0 += k1;  x1 += ks2 + 4u;
  HRND(13) HRND(15) HRND(26) HRND(6)   x0 += ks2; x1 += k0  + 5u;
#undef HRND
  o0 = x0; o1 = x1;
}

// ---------------- launcher ----------------
extern "C" void kernel_launch(void* const* d_in, const int* in_sizes, int n_in,
                              void* d_out, int out_size) {
  const float* ar_in   = (const float*)d_in[0];
  const int*   action  = (const int*)  d_in[1];
  const float* emb     = (const float*)d_in[2];
  const float* Wf      = (const float*)d_in[3];
  const float* bf      = (const float*)d_in[4];
  const float* Wk      = (const float*)d_in[5];
  const float* bk      = (const float*)d_in[6];
  const float* W1      = (const float*)d_in[7];
  const float* b1      = (const float*)d_in[8];
  const float* W2      = (const float*)d_in[9];
  const float* b2      = (const float*)d_in[10];
  const float* Wx      = (const float*)d_in[11];
  const float* Wh      = (const float*)d_in[12];
  const float* bl      = (const float*)d_in[13];
  const float* Wp      = (const float*)d_in[14];
  const float* bp      = (const float*)d_in[15];
  const float* table   = (const float*)d_in[16];
  const float* selt    = (const float*)d_in[17];
  float* out = (float*)d_out;

  SubKeys sk;
  {
    uint32_t k0 = 0u, k1 = 42u;
    for (int s = 0; s < NSTEPS; s++) {
      uint32_t n0, n1, s0, s1;
      h_tf2x32(k0, k1, 0u, 0u, n0, n1);
      h_tf2x32(k0, k1, 0u, 1u, s0, s1);
      sk.a[s] = s0; sk.b[s] = s1;
      k0 = n0; k1 = n1;
    }
  }

  cudaFuncSetAttribute(persist_kernel, cudaFuncAttributeMaxDynamicSharedMemorySize,
                       SMEM_FLOATS * (int)sizeof(float));

  // Fork: gumbel + xpart/wpw1 on the side stream; keyproj/action/func on main.
  static cudaStream_t side = nullptr;
  static cudaEvent_t evFork = nullptr, evJoin = nullptr;
  if (side == nullptr) {
    cudaStreamCreateWithFlags(&side, cudaStreamNonBlocking);
    cudaEventCreateWithFlags(&evFork, cudaEventDisableTiming);
    cudaEventCreateWithFlags(&evJoin, cudaEventDisableTiming);
  }

  cudaEventRecord(evFork, 0);
  cudaStreamWaitEvent(side, evFork, 0);

  gumbel_kernel<<<8192, 256, 0, side>>>(sk);
  precompute_side_kernel<<<GEMM_BLKS + WPW1_BLKS, 256, 0, side>>>(Wp, bp, W1, ar_in, b1);
  precompute_main_kernel<<<KP_BLKS + 1 + FUNC_BLKS, 256>>>(
      action, emb, Wk, bk, Wf, bf, table);

  cudaEventRecord(evJoin, side);
  cudaStreamWaitEvent(0, evJoin, 0);

  persist_kernel<<<256, 256, SMEM_FLOATS * sizeof(float)>>>(
      ar_in, W2, b2, Wx, Wh, bl, Wp, bp, selt, out);
}

// round 15
// speedup vs baseline: 1.0716x; 1.0716x over previous
#include <cuda_runtime.h>
#include <stdint.h>

#define NB 256
#define NE 512
#define NC 256
#define NAR 1024
#define NH 256
#define NK 32
#define NSTEPS 64

typedef unsigned long long ull;

// ---------------- static device scratch ----------------
__device__ float g_xpart[8 * NB * NH];
__device__ float g_WpW1[NK * NH];
__device__ float g_bpW1[NH];
__device__ float g_kpT[(size_t)NB * NE * NK];          // 16 MB, layout [b][e][h]
__device__ float g_func[NB * NH];
__device__ float g_gumbel[(size_t)NB * NSTEPS * NE];   // 32 MB, layout [b][s][e]
__device__ int   g_action[NB];

#define OFF_UNITS ((size_t)NB * NSTEPS * NE)
#define OFF_AR    (OFF_UNITS + (size_t)NB * NSTEPS)

struct SubKeys { unsigned int a[64]; unsigned int b[64]; };

// ---------------- f32x2 packed helpers ----------------
__device__ __forceinline__ void ffma2(ull &d, ull a, ull b) {
  asm("fma.rn.f32x2 %0, %1, %2, %3;" : "=l"(d) : "l"(a), "l"(b), "l"(d));
}
__device__ __forceinline__ ull fadd2(ull a, ull b) {
  ull r; asm("add.rn.f32x2 %0, %1, %2;" : "=l"(r) : "l"(a), "l"(b)); return r;
}
__device__ __forceinline__ ull dup2(float x) {
  ull r; asm("mov.b64 %0, {%1, %1};" : "=l"(r) : "f"(x)); return r;
}
__device__ __forceinline__ ull pack2(float x, float y) {
  ull r; asm("mov.b64 %0, {%1, %2};" : "=l"(r) : "f"(x), "f"(y)); return r;
}
__device__ __forceinline__ float2 unpack2(ull v) {
  float2 r; asm("mov.b64 {%0, %1}, %2;" : "=f"(r.x), "=f"(r.y) : "l"(v)); return r;
}

// ---------------- Threefry-2x32 (20 rounds), device ----------------
__device__ __forceinline__ void tf2x32(uint32_t k0, uint32_t k1,
                                       uint32_t x0, uint32_t x1,
                                       uint32_t &o0, uint32_t &o1) {
  uint32_t ks2 = k0 ^ k1 ^ 0x1BD11BDAu;
  x0 += k0; x1 += k1;
#define RND(r) { x0 += x1; x1 = __funnelshift_l(x1, x1, (r)); x1 ^= x0; }
  RND(13) RND(15) RND(26) RND(6)   x0 += k1;  x1 += ks2 + 1u;
  RND(17) RND(29) RND(16) RND(24)  x0 += ks2; x1 += k0  + 2u;
  RND(13) RND(15) RND(26) RND(6)   x0 += k0;  x1 += k1  + 3u;
  RND(17) RND(29) RND(16) RND(24)  x0 += k1;  x1 += ks2 + 4u;
  RND(13) RND(15) RND(26) RND(6)   x0 += ks2; x1 += k0  + 5u;
#undef RND
  o0 = x0; o1 = x1;
}

__device__ __forceinline__ float gumbelize(uint32_t bits) {
  float f = __uint_as_float((bits >> 9) | 0x3f800000u) - 1.0f;
  f = fmaxf(f, 1e-20f);
  return -__logf(-__logf(f));
}

__device__ __forceinline__ unsigned fenc(float f) {
  unsigned u = __float_as_uint(f);
  return (u & 0x80000000u) ? ~u : (u | 0x80000000u);
}

// ---------------- gumbel kernel (side stream) ----------------
__global__ void gumbel_kernel(SubKeys sk) {
  int v0 = (blockIdx.x * 256 + threadIdx.x) * 4;
  int b = v0 >> 15;
  int rem = v0 & 32767;
  int s = rem >> 9;
  int e = rem & 511;
  int j = b * 512 + e;
  uint32_t k0 = sk.a[s], k1 = sk.b[s];
  float4 r;
  uint32_t o0, o1;
  tf2x32(k0, k1, 0u, (uint32_t)j,     o0, o1); r.x = gumbelize(o0 ^ o1);
  tf2x32(k0, k1, 0u, (uint32_t)(j+1), o0, o1); r.y = gumbelize(o0 ^ o1);
  tf2x32(k0, k1, 0u, (uint32_t)(j+2), o0, o1); r.z = gumbelize(o0 ^ o1);
  tf2x32(k0, k1, 0u, (uint32_t)(j+3), o0, o1); r.w = gumbelize(o0 ^ o1);
  *(float4*)(g_gumbel + (size_t)v0) = r;
}

// ---------------- fused precompute A (main stream) ----------------
#define KP_BLKS   512
#define GEMM_BLKS 256
#define WPW1_BLKS 33
#define FUNC_BLKS 256
__global__ void precompute_kernel(const float* __restrict__ Wp, const float* __restrict__ bp,
                                  const float* __restrict__ W1, const float* __restrict__ ar0,
                                  const int* __restrict__ action_raw,
                                  const float* __restrict__ emb, const float* __restrict__ Wk,
                                  const float* __restrict__ bk, const float* __restrict__ Wf,
                                  const float* __restrict__ bf, const float* __restrict__ table,
                                  const float* __restrict__ b1) {
  __shared__ __align__(16) float psm[8192];
  int blk = blockIdx.x;
  int t = threadIdx.x;

  if (blk < KP_BLKS) {
    int b = blk >> 1, pass = blk & 1;
    for (int i = t; i < NC * NK; i += 256) psm[i] = Wk[i];
    __syncthreads();
    int hg = t & 3, rquad = t >> 2;
    int h0 = hg * 8;
    int r0 = pass * 256 + rquad * 4;
    ull bkp[4];
    #pragma unroll
    for (int j = 0; j < 4; j++) bkp[j] = pack2(bk[h0 + 2*j], bk[h0 + 2*j + 1]);
    ull acc[4][4];
    #pragma unroll
    for (int i = 0; i < 4; i++)
      #pragma unroll
      for (int j = 0; j < 4; j++) acc[i][j] = bkp[j];

    const float* e0p = emb + ((size_t)b * NE + r0) * NC;
    float4 curA0 = __ldcs((const float4*)(e0p));
    float4 curA1 = __ldcs((const float4*)(e0p + NC));
    float4 curA2 = __ldcs((const float4*)(e0p + 2 * NC));
    float4 curA3 = __ldcs((const float4*)(e0p + 3 * NC));
    float4 curB0 = __ldcs((const float4*)(e0p + 4));
    float4 curB1 = __ldcs((const float4*)(e0p + NC + 4));
    float4 curB2 = __ldcs((const float4*)(e0p + 2 * NC + 4));
    float4 curB3 = __ldcs((const float4*)(e0p + 3 * NC + 4));
    for (int c = 0; c < NC; c += 4) {
      float4 e0 = curA0, e1 = curA1, e2 = curA2, e3 = curA3;
      curA0 = curB0; curA1 = curB1; curA2 = curB2; curA3 = curB3;
      if (c + 8 < NC) {
        curB0 = __ldcs((const float4*)(e0p + c + 8));
        curB1 = __ldcs((const float4*)(e0p + NC + c + 8));
        curB2 = __ldcs((const float4*)(e0p + 2 * NC + c + 8));
        curB3 = __ldcs((const float4*)(e0p + 3 * NC + c + 8));
      }
      #pragma unroll
      for (int cc = 0; cc < 4; cc++) {
        const float* wp = psm + (c + cc) * 32 + h0;
        // 8 consecutive aligned floats: two LDS.128 instead of four LDS.64
        float4 wlo = *(const float4*)(wp);
        float4 whi = *(const float4*)(wp + 4);
        ull w0 = ((const ull*)&wlo)[0];
        ull w1 = ((const ull*)&wlo)[1];
        ull w2 = ((const ull*)&whi)[0];
        ull w3 = ((const ull*)&whi)[1];
        ull a0 = dup2(((const float*)&e0)[cc]);
        ull a1 = dup2(((const float*)&e1)[cc]);
        ull a2 = dup2(((const float*)&e2)[cc]);
        ull a3 = dup2(((const float*)&e3)[cc]);
        ffma2(acc[0][0], a0, w0); ffma2(acc[0][1], a0, w1); ffma2(acc[0][2], a0, w2); ffma2(acc[0][3], a0, w3);
        ffma2(acc[1][0], a1, w0); ffma2(acc[1][1], a1, w1); ffma2(acc[1][2], a1, w2); ffma2(acc[1][3], a1, w3);
        ffma2(acc[2][0], a2, w0); ffma2(acc[2][1], a2, w1); ffma2(acc[2][2], a2, w2); ffma2(acc[2][3], a2, w3);
        ffma2(acc[3][0], a3, w0); ffma2(acc[3][1], a3, w1); ffma2(acc[3][2], a3, w2); ffma2(acc[3][3], a3, w3);
      }
    }
    float* kpb = g_kpT + (size_t)b * (NE * NK);
    #pragma unroll
    for (int i = 0; i < 4; i++)
      #pragma unroll
      for (int j = 0; j < 4; j++)
        *(ull*)(kpb + (size_t)(r0 + i) * NK + h0 + 2 * j) = acc[i][j];
  } else if (blk < KP_BLKS + GEMM_BLKS) {
    int flat = blk - KP_BLKS;
    int bx = flat & 3, by = (flat >> 2) & 7, bz = flat >> 5;
    float* As = psm;
    float* Bs = psm + 528;
    int bm = by * 32, bn = bx * 64, k0 = bz * 128;
    int ty = t >> 4, tx = t & 15;
    float acc[2][4] = {{0.f,0.f,0.f,0.f},{0.f,0.f,0.f,0.f}};
    for (int kc = 0; kc < 128; kc += 16) {
      {
        int m = t >> 3;
        int kk = (t & 7) * 2;
        const float* p = ar0 + (size_t)(bm + m) * NAR + (k0 + kc + kk);
        As[kk * 33 + m] = p[0];
        As[(kk + 1) * 33 + m] = p[1];
      }
      {
        int kk = t >> 4;
        int j = (t & 15) * 4;
        const float* p = W1 + (size_t)(k0 + kc + kk) * NH + bn + j;
        Bs[kk * 68 + j] = p[0]; Bs[kk * 68 + j+1] = p[1]; Bs[kk * 68 + j+2] = p[2]; Bs[kk * 68 + j+3] = p[3];
      }
      __syncthreads();
      #pragma unroll
      for (int k = 0; k < 16; k++) {
        float a0 = As[k * 33 + ty * 2], a1 = As[k * 33 + ty * 2 + 1];
        float4 bv = *reinterpret_cast<const float4*>(&Bs[k * 68 + tx * 4]);
        acc[0][0] += a0 * bv.x; acc[0][1] += a0 * bv.y; acc[0][2] += a0 * bv.z; acc[0][3] += a0 * bv.w;
        acc[1][0] += a1 * bv.x; acc[1][1] += a1 * bv.y; acc[1][2] += a1 * bv.z; acc[1][3] += a1 * bv.w;
      }
      __syncthreads();
    }
    float* xp = g_xpart + (size_t)bz * (NB * NH);
    #pragma unroll
    for (int im = 0; im < 2; im++) {
      int row = bm + ty * 2 + im;
      float* o = xp + (size_t)row * NH + bn + tx * 4;
      float bb0 = (bz == 0) ? b1[bn + tx * 4]     : 0.f;
      float bb1 = (bz == 0) ? b1[bn + tx * 4 + 1] : 0.f;
      float bb2 = (bz == 0) ? b1[bn + tx * 4 + 2] : 0.f;
      float bb3 = (bz == 0) ? b1[bn + tx * 4 + 3] : 0.f;
      o[0] = acc[im][0] + bb0; o[1] = acc[im][1] + bb1;
      o[2] = acc[im][2] + bb2; o[3] = acc[im][3] + bb3;
    }
  } else if (blk < KP_BLKS + GEMM_BLKS + WPW1_BLKS) {
    float* s_row = psm;
    int i = blk - (KP_BLKS + GEMM_BLKS);
    for (int k = t; k < NAR; k += 256)
      s_row[k] = (i < NK) ? Wp[(size_t)i * NAR + k] : bp[k];
    __syncthreads();
    float a0 = 0.f, a1 = 0.f, a2 = 0.f, a3 = 0.f;
    for (int k = 0; k < NAR; k += 4) {
      a0 += s_row[k]     * W1[(size_t)k * NH + t];
      a1 += s_row[k + 1] * W1[(size_t)(k + 1) * NH + t];
      a2 += s_row[k + 2] * W1[(size_t)(k + 2) * NH + t];
      a3 += s_row[k + 3] * W1[(size_t)(k + 3) * NH + t];
    }
    float acc = (a0 + a1) + (a2 + a3);
    if (i < NK) g_WpW1[i * NH + t] = acc; else g_bpW1[t] = acc;
  } else if (blk == KP_BLKS + GEMM_BLKS + WPW1_BLKS) {
    int odd = (t < 128) ? action_raw[2 * t + 1] : 0;
    int any = __syncthreads_or(odd != 0);
    g_action[t] = any ? action_raw[t] : action_raw[2 * t];
  } else {
    int b = blk - (KP_BLKS + GEMM_BLKS + WPW1_BLKS + 1);
    int odd = (t < 128) ? action_raw[2 * t + 1] : 0;
    int any = __syncthreads_or(odd != 0);
    int a = any ? action_raw[b] : action_raw[2 * b];
    psm[t] = table[(size_t)a * 256 + t];
    __syncthreads();
    float a0 = 0.f, a1 = 0.f;
    #pragma unroll 4
    for (int k = 0; k < 256; k += 2) {
      a0 = fmaf(psm[k],     Wf[(size_t)k * 256 + t], a0);
      a1 = fmaf(psm[k + 1], Wf[(size_t)(k + 1) * 256 + t], a1);
    }
    g_func[b * 256 + t] = fmaxf(bf[t] + a0 + a1, 0.0f);
  }
}

// ---------------- persistent per-batch kernel (known-good 172us version) ----------------
#define KPT_S    514
#define OFF_KPT  0
#define OFF_WXH  16448
#define OFF_ZR   24704
#define OFF_T    24960
#define OFF_PART 25216
#define OFF_H    25344
#define OFF_HD   25376
#define OFF_RED  25440
#define OFF_KEY  25456
#define OFF_SUM  25472
#define SMEM_FLOATS 25504

__global__ __launch_bounds__(256, 2) void persist_kernel(
    const float* __restrict__ ar0,
    const float* __restrict__ W2, const float* __restrict__ b2,
    const float* __restrict__ Wx, const float* __restrict__ Wh,
    const float* __restrict__ bl, const float* __restrict__ Wp,
    const float* __restrict__ bp,
    const float* __restrict__ selt, float* __restrict__ out)
{
  extern __shared__ float sm[];
  float* s_kpT  = sm + OFF_KPT;
  float* s_Wxh  = sm + OFF_WXH;
  float* s_zred = sm + OFF_ZR;
  float* s_t    = sm + OFF_T;
  float* s_part = sm + OFF_PART;
  float* s_h    = sm + OFF_H;
  ull*   s_hd   = (ull*)(sm + OFF_HD);
  float* s_red  = sm + OFF_RED;
  ull*   s_key  = (ull*)(sm + OFF_KEY);
  float* s_sum  = sm + OFF_SUM;

  int b = blockIdx.x, t = threadIdx.x;
  int lane = t & 31, wid = t >> 5;

  float sel = selt[g_action[b]];

  // ======== prologue ========
  {
    const float* kpg = g_kpT + (size_t)b * (NE * NK);
    #pragma unroll
    for (int i = t * 4; i < NE * NK; i += 1024) {
      float4 v = *(const float4*)(kpg + i);
      int e = i >> 5, h = i & 31;
      s_kpT[(h + 0) * KPT_S + e] = v.x;
      s_kpT[(h + 1) * KPT_S + e] = v.y;
      s_kpT[(h + 2) * KPT_S + e] = v.z;
      s_kpT[(h + 3) * KPT_S + e] = v.w;
    }
  }
  for (int i = t; i < 4096; i += 256) {
    int k = i >> 7, col = i & 127;
    int g = col >> 5, h = col & 31;
    s_Wxh[k * 258 + h * 8 + g * 2]     = Wx[i];
    s_Wxh[k * 258 + h * 8 + g * 2 + 1] = Wh[i];
  }
  if (t < 32) { s_h[t] = 0.0f; s_hd[t] = 0ull; }

  float func_r = g_func[b * 256 + t];
  float x_r = g_xpart[b * NH + t];      // includes b1 (folded in precompute)
  #pragma unroll
  for (int p = 1; p < 8; p++) x_r += g_xpart[p * (NB * NH) + b * NH + t];

  float wpw1r[32];
  ull w2p[16];
  float csum = 0.f;
  #pragma unroll
  for (int k = 0; k < 32; k++) { wpw1r[k] = g_WpW1[k * NH + t]; csum += wpw1r[k]; }
  #pragma unroll
  for (int j = 0; j < 16; j++)
    w2p[j] = pack2(W2[(size_t)(wid * 32 + 2*j) * 32 + lane],
                   W2[(size_t)(wid * 32 + 2*j + 1) * 32 + lane]);
  float bpw1c = g_bpW1[t] - 0.001953125f * csum;
  float b2r = b2[lane];

  int khalf = wid >> 2;
  int lh = (wid & 3) * 8 + (lane >> 2);
  int lg = lane & 3;
  float blr = bl[lg * 32 + lh];
  float creg = 0.f, sumr = 0.f;
  float m0 = 1.0f, m1 = 1.0f;
  __syncthreads();

  const float* gumbase = g_gumbel + (size_t)b * (NSTEPS * NE) + 2 * t;

  // ======== 64-step loop ========
  for (int s = 0; s < NSTEPS; s++) {
    float2 gpair = *(const float2*)(gumbase + s * NE);
    float hpreg = s_h[lane];

    if (s > 0) {
      ull kk = s_key[0];
      #pragma unroll
      for (int i = 1; i < 8; i++) { ull o = s_key[i]; if (o > kk) kk = o; }
      int id = (int)(0xFFFFFFFFu - (unsigned)(kk & 0xFFFFFFFFull));
      if (id == 2 * t) m0 = 0.0f;
      if (id == 2 * t + 1) m1 = 0.0f;
      const float* kc = s_kpT + id;
      float xv0 = x_r + bpw1c, xv1 = 0.f, xv2 = 0.f, xv3 = 0.f;
      #pragma unroll
      for (int k = 0; k < 32; k += 4) {
        xv0 = fmaf(kc[(k + 0) * KPT_S], wpw1r[k + 0], xv0);
        xv1 = fmaf(kc[(k + 1) * KPT_S], wpw1r[k + 1], xv1);
        xv2 = fmaf(kc[(k + 2) * KPT_S], wpw1r[k + 2], xv2);
        xv3 = fmaf(kc[(k + 3) * KPT_S], wpw1r[k + 3], xv3);
      }
      x_r = (xv0 + xv1) + (xv2 + xv3);
      if (wid == 0) sumr += s_kpT[lane * KPT_S + id] - 0.001953125f;
      if (t == 0) out[OFF_UNITS + (size_t)b * NSTEPS + (s - 1)] = (float)id * sel;
    }
    float tval = fmaxf(func_r + x_r, 0.0f);
    s_t[t] = tval;
    __syncwarp();
    {
      const ull* tp = (const ull*)(s_t + wid * 32);
      ull za = 0ull, zb = 0ull;
      #pragma unroll
      for (int j = 0; j < 16; j += 2) {
        ffma2(za, tp[j], w2p[j]);
        ffma2(zb, tp[j + 1], w2p[j + 1]);
      }
      float2 zv = unpack2(fadd2(za, zb));
      s_zred[t] = zv.x + zv.y;
    }
    __syncthreads();

    float z2l;
    {
      float r0 = s_zred[lane]        + s_zred[32 + lane];
      float r1 = s_zred[64 + lane]   + s_zred[96 + lane];
      float r2 = s_zred[128 + lane]  + s_zred[160 + lane];
      float r3 = s_zred[192 + lane]  + s_zred[224 + lane];
      z2l = b2r + ((r0 + r1) + (r2 + r3));
    }
    {
      float accA = (khalf == 0) ? blr : 0.f, accB = 0.f;
      const float* wbase = s_Wxh + lh * 8 + lg * 2 + khalf * (16 * 258);
      #pragma unroll
      for (int k16 = 0; k16 < 16; k16 += 2) {
        int k = khalf * 16 + k16;
        float z2a = __shfl_sync(0xffffffffu, z2l, k);
        float ha  = __shfl_sync(0xffffffffu, hpreg, k);
        float2 wa = unpack2(*(const ull*)(wbase + k16 * 258));
        accA = fmaf(z2a, wa.x, fmaf(ha, wa.y, accA));
        float z2b = __shfl_sync(0xffffffffu, z2l, k + 1);
        float hb  = __shfl_sync(0xffffffffu, hpreg, k + 1);
        float2 wb = unpack2(*(const ull*)(wbase + (k16 + 1) * 258));
        accB = fmaf(z2b, wb.x, fmaf(hb, wb.y, accB));
      }
      float acc = accA + accB;
      if (khalf == 1) s_part[lh * 4 + lg] = acc;
      __syncthreads();
      if (khalf == 0) {
        acc += s_part[lh * 4 + lg];
        float e2 = __expf((lg == 2) ? (2.f * acc) : (-acc));
        float tg = (lg == 2) ? (1.f - __fdividef(2.f, e2 + 1.f))
                             : __fdividef(1.f, 1.f + e2);
        int base = lane & ~3;
        float iv = __shfl_sync(0xffffffffu, tg, base);
        float fv = __shfl_sync(0xffffffffu, tg, base + 1);
        float gv = __shfl_sync(0xffffffffu, tg, base + 2);
        float ov = __shfl_sync(0xffffffffu, tg, base + 3);
        creg = fv * creg + iv * gv;
        float e2c = __expf(2.f * creg);
        float hv = ov * (1.f - __fdividef(2.f, e2c + 1.f));
        if (lg == 0) { s_h[lh] = hv; s_hd[lh] = dup2(hv); }
      }
    }
    __syncthreads();

    ull a0 = 0ull, a1 = 0ull, a2 = 0ull, a3 = 0ull;
    {
      const float* kb = s_kpT + 2 * t;
      #pragma unroll
      for (int q = 0; q < 8; q++) {
        ffma2(a0, *(const ull*)(kb + (4*q + 0) * KPT_S), s_hd[4*q + 0]);
        ffma2(a1, *(const ull*)(kb + (4*q + 1) * KPT_S), s_hd[4*q + 1]);
        ffma2(a2, *(const ull*)(kb + (4*q + 2) * KPT_S), s_hd[4*q + 2]);
        ffma2(a3, *(const ull*)(kb + (4*q + 3) * KPT_S), s_hd[4*q + 3]);
      }
    }
    float2 yv = unpack2(fadd2(fadd2(a0, a1), fadd2(a2, a3)));
    float y0 = yv.x * m0, y1 = yv.y * m1;
    __stcs((float2*)(out + ((size_t)b * NSTEPS + s) * NE + 2 * t),
           make_float2(y0 * sel, y1 * sel));
    float p0 = __expf(y0), p1 = __expf(y1);
    float ssum = p0 + p1;
    #pragma unroll
    for (int o = 16; o; o >>= 1) ssum += __shfl_xor_sync(0xffffffffu, ssum, o);
    if (lane == 0) s_red[wid] = ssum;
    __syncthreads();

    float S;
    {
      float r0 = s_red[0] + s_red[1], r1 = s_red[2] + s_red[3];
      float r2 = s_red[4] + s_red[5], r3 = s_red[6] + s_red[7];
      S = (r0 + r1) + (r2 + r3);
    }
    float v0 = fmaf(S, gpair.x, p0);
    float v1 = fmaf(S, gpair.y, p1);
    ull kA = ((ull)fenc(v0) << 32) | (ull)(0xFFFFFFFFu - (unsigned)(2 * t));
    ull kB = ((ull)fenc(v1) << 32) | (ull)(0xFFFFFFFFu - (unsigned)(2 * t + 1));
    ull km = (kA > kB) ? kA : kB;
    #pragma unroll
    for (int o = 16; o; o >>= 1) {
      ull other = __shfl_xor_sync(0xffffffffu, km, o);
      if (other > km) km = other;
    }
    if (lane == 0) s_key[wid] = km;
    __syncthreads();
  }

  // ======== final selection ========
  {
    ull kk = s_key[0];
    #pragma unroll
    for (int i = 1; i < 8; i++) { ull o = s_key[i]; if (o > kk) kk = o; }
    int id = (int)(0xFFFFFFFFu - (unsigned)(kk & 0xFFFFFFFFull));
    if (wid == 0) sumr += s_kpT[lane * KPT_S + id] - 0.001953125f;
    if (t == 0) out[OFF_UNITS + (size_t)b * NSTEPS + (NSTEPS - 1)] = (float)id * sel;
  }
  if (wid == 0) s_sum[lane] = sumr;
  __syncthreads();

  // ======== epilogue ========
  for (int j = t; j < NAR; j += 256) {
    float acc0 = ar0[(size_t)b * NAR + j] + 64.0f * bp[j];
    float acc1 = 0.f, acc2 = 0.f, acc3 = 0.f;
    #pragma unroll
    for (int k = 0; k < 32; k += 4) {
      acc0 = fmaf(s_sum[k + 0], Wp[(size_t)(k + 0) * NAR + j], acc0);
      acc1 = fmaf(s_sum[k + 1], Wp[(size_t)(k + 1) * NAR + j], acc1);
      acc2 = fmaf(s_sum[k + 2], Wp[(size_t)(k + 2) * NAR + j], acc2);
      acc3 = fmaf(s_sum[k + 3], Wp[(size_t)(k + 3) * NAR + j], acc3);
    }
    __stcs(out + OFF_AR + (size_t)b * NAR + j, ((acc0 + acc1) + (acc2 + acc3)) * sel);
  }
}

// ---------------- host threefry ----------------
static inline void h_tf2x32(uint32_t k0, uint32_t k1, uint32_t x0, uint32_t x1,
                            uint32_t &o0, uint32_t &o1) {
  uint32_t ks2 = k0 ^ k1 ^ 0x1BD11BDAu;
  x0 += k0; x1 += k1;
#define HRND(r) { x0 += x1; x1 = (x1 << (r)) | (x1 >> (32 - (r))); x1 ^= x0; }
  HRND(13) HRND(15) HRND(26) HRND(6)   x0 += k1;  x1 += ks2 + 1u;
  HRND(17) HRND(29) HRND(16) HRND(24)  x0 += ks2; x1 += k0  + 2u;
  HRND(13) HRND(15) HRND(26) HRND(6)   x0 += k0;  x1 += k1  + 3u;
  HRND(17) HRND(29) HRND(16) HRND(24)  x0 += k1;  x1 += ks2 + 4u;
  HRND(13) HRND(15) HRND(26) HRND(6)   x0 += ks2; x1 += k0  + 5u;
#undef HRND
  o0 = x0; o1 = x1;
}

// ---------------- launcher ----------------
extern "C" void kernel_launch(void* const* d_in, const int* in_sizes, int n_in,
                              void* d_out, int out_size) {
  const float* ar_in   = (const float*)d_in[0];
  const int*   action  = (const int*)  d_in[1];
  const float* emb     = (const float*)d_in[2];
  const float* Wf      = (const float*)d_in[3];
  const float* bf      = (const float*)d_in[4];
  const float* Wk      = (const float*)d_in[5];
  const float* bk      = (const float*)d_in[6];
  const float* W1      = (const float*)d_in[7];
  const float* b1      = (const float*)d_in[8];
  const float* W2      = (const float*)d_in[9];
  const float* b2      = (const float*)d_in[10];
  const float* Wx      = (const float*)d_in[11];
  const float* Wh      = (const float*)d_in[12];
  const float* bl      = (const float*)d_in[13];
  const float* Wp      = (const float*)d_in[14];
  const float* bp      = (const float*)d_in[15];
  const float* table   = (const float*)d_in[16];
  const float* selt    = (const float*)d_in[17];
  float* out = (float*)d_out;

  SubKeys sk;
  {
    uint32_t k0 = 0u, k1 = 42u;
    for (int s = 0; s < NSTEPS; s++) {
      uint32_t n0, n1, s0, s1;
      h_tf2x32(k0, k1, 0u, 0u, n0, n1);
      h_tf2x32(k0, k1, 0u, 1u, s0, s1);
      sk.a[s] = s0; sk.b[s] = s1;
      k0 = n0; k1 = n1;
    }
  }

  cudaFuncSetAttribute(persist_kernel, cudaFuncAttributeMaxDynamicSharedMemorySize,
                       SMEM_FLOATS * (int)sizeof(float));

  // Fork: gumbel on a side stream, parallel with fused precompute-A; join before persist.
  static cudaStream_t side = nullptr;
  static cudaEvent_t evFork = nullptr, evJoin = nullptr;
  if (side == nullptr) {
    cudaStreamCreateWithFlags(&side, cudaStreamNonBlocking);
    cudaEventCreateWithFlags(&evFork, cudaEventDisableTiming);
    cudaEventCreateWithFlags(&evJoin, cudaEventDisableTiming);
  }

  cudaEventRecord(evFork, 0);
  cudaStreamWaitEvent(side, evFork, 0);

  gumbel_kernel<<<8192, 256, 0, side>>>(sk);
  precompute_kernel<<<KP_BLKS + GEMM_BLKS + WPW1_BLKS + 1 + FUNC_BLKS, 256>>>(
      Wp, bp, W1, ar_in, action, emb, Wk, bk, Wf, bf, table, b1);

  cudaEventRecord(evJoin, side);
  cudaStreamWaitEvent(0, evJoin, 0);

  persist_kernel<<<256, 256, SMEM_FLOATS * sizeof(float)>>>(
      ar_in, W2, b2, Wx, Wh, bl, Wp, bp, selt, out);
}

// round 16
// speedup vs baseline: 1.0861x; 1.0135x over previous
#include <cuda_runtime.h>
#include <stdint.h>

#define NB 256
#define NE 512
#define NC 256
#define NAR 1024
#define NH 256
#define NK 32
#define NSTEPS 64

typedef unsigned long long ull;

// ---------------- static device scratch ----------------
__device__ float g_xpart[8 * NB * NH];
__device__ float g_WpW1[NK * NH];
__device__ float g_bpW1[NH];
__device__ float g_kpT[(size_t)NB * NE * NK];          // 16 MB, layout [b][e][h]
__device__ float g_func[NB * NH];
__device__ float g_gumbel[(size_t)NB * NSTEPS * NE];   // 32 MB, layout [b][s][e]
__device__ int   g_action[NB];

#define OFF_UNITS ((size_t)NB * NSTEPS * NE)
#define OFF_AR    (OFF_UNITS + (size_t)NB * NSTEPS)

struct SubKeys { unsigned int a[64]; unsigned int b[64]; };

// ---------------- f32x2 packed helpers ----------------
__device__ __forceinline__ void ffma2(ull &d, ull a, ull b) {
  asm("fma.rn.f32x2 %0, %1, %2, %3;" : "=l"(d) : "l"(a), "l"(b), "l"(d));
}
__device__ __forceinline__ ull fadd2(ull a, ull b) {
  ull r; asm("add.rn.f32x2 %0, %1, %2;" : "=l"(r) : "l"(a), "l"(b)); return r;
}
__device__ __forceinline__ ull dup2(float x) {
  ull r; asm("mov.b64 %0, {%1, %1};" : "=l"(r) : "f"(x)); return r;
}
__device__ __forceinline__ ull pack2(float x, float y) {
  ull r; asm("mov.b64 %0, {%1, %2};" : "=l"(r) : "f"(x), "f"(y)); return r;
}
__device__ __forceinline__ float2 unpack2(ull v) {
  float2 r; asm("mov.b64 {%0, %1}, %2;" : "=f"(r.x), "=f"(r.y) : "l"(v)); return r;
}

// ---------------- Threefry-2x32 (20 rounds), device ----------------
__device__ __forceinline__ void tf2x32(uint32_t k0, uint32_t k1,
                                       uint32_t x0, uint32_t x1,
                                       uint32_t &o0, uint32_t &o1) {
  uint32_t ks2 = k0 ^ k1 ^ 0x1BD11BDAu;
  x0 += k0; x1 += k1;
#define RND(r) { x0 += x1; x1 = __funnelshift_l(x1, x1, (r)); x1 ^= x0; }
  RND(13) RND(15) RND(26) RND(6)   x0 += k1;  x1 += ks2 + 1u;
  RND(17) RND(29) RND(16) RND(24)  x0 += ks2; x1 += k0  + 2u;
  RND(13) RND(15) RND(26) RND(6)   x0 += k0;  x1 += k1  + 3u;
  RND(17) RND(29) RND(16) RND(24)  x0 += k1;  x1 += ks2 + 4u;
  RND(13) RND(15) RND(26) RND(6)   x0 += ks2; x1 += k0  + 5u;
#undef RND
  o0 = x0; o1 = x1;
}

__device__ __forceinline__ float gumbelize(uint32_t bits) {
  float f = __uint_as_float((bits >> 9) | 0x3f800000u) - 1.0f;
  f = fmaxf(f, 1e-20f);
  return -__logf(-__logf(f));
}

__device__ __forceinline__ unsigned fenc(float f) {
  unsigned u = __float_as_uint(f);
  return (u & 0x80000000u) ? ~u : (u | 0x80000000u);
}

// ---------------- gumbel kernel (side stream) ----------------
__global__ void gumbel_kernel(SubKeys sk) {
  int v0 = (blockIdx.x * 256 + threadIdx.x) * 4;
  int b = v0 >> 15;
  int rem = v0 & 32767;
  int s = rem >> 9;
  int e = rem & 511;
  int j = b * 512 + e;
  uint32_t k0 = sk.a[s], k1 = sk.b[s];
  float4 r;
  uint32_t o0, o1;
  tf2x32(k0, k1, 0u, (uint32_t)j,     o0, o1); r.x = gumbelize(o0 ^ o1);
  tf2x32(k0, k1, 0u, (uint32_t)(j+1), o0, o1); r.y = gumbelize(o0 ^ o1);
  tf2x32(k0, k1, 0u, (uint32_t)(j+2), o0, o1); r.z = gumbelize(o0 ^ o1);
  tf2x32(k0, k1, 0u, (uint32_t)(j+3), o0, o1); r.w = gumbelize(o0 ^ o1);
  *(float4*)(g_gumbel + (size_t)v0) = r;
}

// ---------------- fused precompute A (main stream) ----------------
#define KP_BLKS   512
#define GEMM_BLKS 256
#define WPW1_BLKS 33
#define FUNC_BLKS 256
__global__ void precompute_kernel(const float* __restrict__ Wp, const float* __restrict__ bp,
                                  const float* __restrict__ W1, const float* __restrict__ ar0,
                                  const int* __restrict__ action_raw,
                                  const float* __restrict__ emb, const float* __restrict__ Wk,
                                  const float* __restrict__ bk, const float* __restrict__ Wf,
                                  const float* __restrict__ bf, const float* __restrict__ table,
                                  const float* __restrict__ b1) {
  __shared__ __align__(16) float psm[8192];
  int blk = blockIdx.x;
  int t = threadIdx.x;

  if (blk < KP_BLKS) {
    int b = blk >> 1, pass = blk & 1;
    for (int i = t; i < NC * NK; i += 256) psm[i] = Wk[i];
    __syncthreads();
    int hg = t & 3, rquad = t >> 2;
    int h0 = hg * 8;
    int r0 = pass * 256 + rquad * 4;
    ull bkp[4];
    #pragma unroll
    for (int j = 0; j < 4; j++) bkp[j] = pack2(bk[h0 + 2*j], bk[h0 + 2*j + 1]);
    ull acc[4][4];
    #pragma unroll
    for (int i = 0; i < 4; i++)
      #pragma unroll
      for (int j = 0; j < 4; j++) acc[i][j] = bkp[j];

    const float* e0p = emb + ((size_t)b * NE + r0) * NC;
    float4 curA0 = __ldcs((const float4*)(e0p));
    float4 curA1 = __ldcs((const float4*)(e0p + NC));
    float4 curA2 = __ldcs((const float4*)(e0p + 2 * NC));
    float4 curA3 = __ldcs((const float4*)(e0p + 3 * NC));
    float4 curB0 = __ldcs((const float4*)(e0p + 4));
    float4 curB1 = __ldcs((const float4*)(e0p + NC + 4));
    float4 curB2 = __ldcs((const float4*)(e0p + 2 * NC + 4));
    float4 curB3 = __ldcs((const float4*)(e0p + 3 * NC + 4));
    for (int c = 0; c < NC; c += 4) {
      float4 e0 = curA0, e1 = curA1, e2 = curA2, e3 = curA3;
      curA0 = curB0; curA1 = curB1; curA2 = curB2; curA3 = curB3;
      if (c + 8 < NC) {
        curB0 = __ldcs((const float4*)(e0p + c + 8));
        curB1 = __ldcs((const float4*)(e0p + NC + c + 8));
        curB2 = __ldcs((const float4*)(e0p + 2 * NC + c + 8));
        curB3 = __ldcs((const float4*)(e0p + 3 * NC + c + 8));
      }
      #pragma unroll
      for (int cc = 0; cc < 4; cc++) {
        const float* wp = psm + (c + cc) * 32 + h0;
        ull w0 = *(const ull*)(wp);
        ull w1 = *(const ull*)(wp + 2);
        ull w2 = *(const ull*)(wp + 4);
        ull w3 = *(const ull*)(wp + 6);
        ull a0 = dup2(((const float*)&e0)[cc]);
        ull a1 = dup2(((const float*)&e1)[cc]);
        ull a2 = dup2(((const float*)&e2)[cc]);
        ull a3 = dup2(((const float*)&e3)[cc]);
        ffma2(acc[0][0], a0, w0); ffma2(acc[0][1], a0, w1); ffma2(acc[0][2], a0, w2); ffma2(acc[0][3], a0, w3);
        ffma2(acc[1][0], a1, w0); ffma2(acc[1][1], a1, w1); ffma2(acc[1][2], a1, w2); ffma2(acc[1][3], a1, w3);
        ffma2(acc[2][0], a2, w0); ffma2(acc[2][1], a2, w1); ffma2(acc[2][2], a2, w2); ffma2(acc[2][3], a2, w3);
        ffma2(acc[3][0], a3, w0); ffma2(acc[3][1], a3, w1); ffma2(acc[3][2], a3, w2); ffma2(acc[3][3], a3, w3);
      }
    }
    float* kpb = g_kpT + (size_t)b * (NE * NK);
    #pragma unroll
    for (int i = 0; i < 4; i++)
      #pragma unroll
      for (int j = 0; j < 4; j++)
        *(ull*)(kpb + (size_t)(r0 + i) * NK + h0 + 2 * j) = acc[i][j];
  } else if (blk < KP_BLKS + GEMM_BLKS) {
    int flat = blk - KP_BLKS;
    int bx = flat & 3, by = (flat >> 2) & 7, bz = flat >> 5;
    float* As = psm;
    float* Bs = psm + 528;
    int bm = by * 32, bn = bx * 64, k0 = bz * 128;
    int ty = t >> 4, tx = t & 15;
    float acc[2][4] = {{0.f,0.f,0.f,0.f},{0.f,0.f,0.f,0.f}};
    for (int kc = 0; kc < 128; kc += 16) {
      {
        int m = t >> 3;
        int kk = (t & 7) * 2;
        const float* p = ar0 + (size_t)(bm + m) * NAR + (k0 + kc + kk);
        As[kk * 33 + m] = p[0];
        As[(kk + 1) * 33 + m] = p[1];
      }
      {
        int kk = t >> 4;
        int j = (t & 15) * 4;
        const float* p = W1 + (size_t)(k0 + kc + kk) * NH + bn + j;
        Bs[kk * 68 + j] = p[0]; Bs[kk * 68 + j+1] = p[1]; Bs[kk * 68 + j+2] = p[2]; Bs[kk * 68 + j+3] = p[3];
      }
      __syncthreads();
      #pragma unroll
      for (int k = 0; k < 16; k++) {
        float a0 = As[k * 33 + ty * 2], a1 = As[k * 33 + ty * 2 + 1];
        float4 bv = *reinterpret_cast<const float4*>(&Bs[k * 68 + tx * 4]);
        acc[0][0] += a0 * bv.x; acc[0][1] += a0 * bv.y; acc[0][2] += a0 * bv.z; acc[0][3] += a0 * bv.w;
        acc[1][0] += a1 * bv.x; acc[1][1] += a1 * bv.y; acc[1][2] += a1 * bv.z; acc[1][3] += a1 * bv.w;
      }
      __syncthreads();
    }
    float* xp = g_xpart + (size_t)bz * (NB * NH);
    #pragma unroll
    for (int im = 0; im < 2; im++) {
      int row = bm + ty * 2 + im;
      float* o = xp + (size_t)row * NH + bn + tx * 4;
      float bb0 = (bz == 0) ? b1[bn + tx * 4]     : 0.f;
      float bb1 = (bz == 0) ? b1[bn + tx * 4 + 1] : 0.f;
      float bb2 = (bz == 0) ? b1[bn + tx * 4 + 2] : 0.f;
      float bb3 = (bz == 0) ? b1[bn + tx * 4 + 3] : 0.f;
      o[0] = acc[im][0] + bb0; o[1] = acc[im][1] + bb1;
      o[2] = acc[im][2] + bb2; o[3] = acc[im][3] + bb3;
    }
  } else if (blk < KP_BLKS + GEMM_BLKS + WPW1_BLKS) {
    float* s_row = psm;
    int i = blk - (KP_BLKS + GEMM_BLKS);
    for (int k = t; k < NAR; k += 256)
      s_row[k] = (i < NK) ? Wp[(size_t)i * NAR + k] : bp[k];
    __syncthreads();
    float a0 = 0.f, a1 = 0.f, a2 = 0.f, a3 = 0.f;
    for (int k = 0; k < NAR; k += 4) {
      a0 += s_row[k]     * W1[(size_t)k * NH + t];
      a1 += s_row[k + 1] * W1[(size_t)(k + 1) * NH + t];
      a2 += s_row[k + 2] * W1[(size_t)(k + 2) * NH + t];
      a3 += s_row[k + 3] * W1[(size_t)(k + 3) * NH + t];
    }
    float acc = (a0 + a1) + (a2 + a3);
    if (i < NK) g_WpW1[i * NH + t] = acc; else g_bpW1[t] = acc;
  } else if (blk == KP_BLKS + GEMM_BLKS + WPW1_BLKS) {
    int odd = (t < 128) ? action_raw[2 * t + 1] : 0;
    int any = __syncthreads_or(odd != 0);
    g_action[t] = any ? action_raw[t] : action_raw[2 * t];
  } else {
    int b = blk - (KP_BLKS + GEMM_BLKS + WPW1_BLKS + 1);
    int odd = (t < 128) ? action_raw[2 * t + 1] : 0;
    int any = __syncthreads_or(odd != 0);
    int a = any ? action_raw[b] : action_raw[2 * b];
    psm[t] = table[(size_t)a * 256 + t];
    __syncthreads();
    float a0 = 0.f, a1 = 0.f;
    #pragma unroll 4
    for (int k = 0; k < 256; k += 2) {
      a0 = fmaf(psm[k],     Wf[(size_t)k * 256 + t], a0);
      a1 = fmaf(psm[k + 1], Wf[(size_t)(k + 1) * 256 + t], a1);
    }
    g_func[b * 256 + t] = fmaxf(bf[t] + a0 + a1, 0.0f);
  }
}

// ---------------- persistent per-batch kernel (known-good 172us version) ----------------
#define KPT_S    514
#define OFF_KPT  0
#define OFF_WXH  16448
#define OFF_ZR   24704
#define OFF_T    24960
#define OFF_PART 25216
#define OFF_H    25344
#define OFF_HD   25376
#define OFF_RED  25440
#define OFF_KEY  25456
#define OFF_SUM  25472
#define SMEM_FLOATS 25504

__global__ __launch_bounds__(256, 2) void persist_kernel(
    const float* __restrict__ ar0,
    const float* __restrict__ W2, const float* __restrict__ b2,
    const float* __restrict__ Wx, const float* __restrict__ Wh,
    const float* __restrict__ bl, const float* __restrict__ Wp,
    const float* __restrict__ bp,
    const float* __restrict__ selt, float* __restrict__ out)
{
  extern __shared__ float sm[];
  float* s_kpT  = sm + OFF_KPT;
  float* s_Wxh  = sm + OFF_WXH;
  float* s_zred = sm + OFF_ZR;
  float* s_t    = sm + OFF_T;
  float* s_part = sm + OFF_PART;
  float* s_h    = sm + OFF_H;
  ull*   s_hd   = (ull*)(sm + OFF_HD);
  float* s_red  = sm + OFF_RED;
  ull*   s_key  = (ull*)(sm + OFF_KEY);
  float* s_sum  = sm + OFF_SUM;

  int b = blockIdx.x, t = threadIdx.x;
  int lane = t & 31, wid = t >> 5;

  float sel = selt[g_action[b]];

  // ======== prologue ========
  {
    const float* kpg = g_kpT + (size_t)b * (NE * NK);
    #pragma unroll
    for (int i = t * 4; i < NE * NK; i += 1024) {
      float4 v = *(const float4*)(kpg + i);
      int e = i >> 5, h = i & 31;
      s_kpT[(h + 0) * KPT_S + e] = v.x;
      s_kpT[(h + 1) * KPT_S + e] = v.y;
      s_kpT[(h + 2) * KPT_S + e] = v.z;
      s_kpT[(h + 3) * KPT_S + e] = v.w;
    }
  }
  for (int i = t; i < 4096; i += 256) {
    int k = i >> 7, col = i & 127;
    int g = col >> 5, h = col & 31;
    s_Wxh[k * 258 + h * 8 + g * 2]     = Wx[i];
    s_Wxh[k * 258 + h * 8 + g * 2 + 1] = Wh[i];
  }
  if (t < 32) { s_h[t] = 0.0f; s_hd[t] = 0ull; }

  float func_r = g_func[b * 256 + t];
  float x_r = g_xpart[b * NH + t];      // includes b1 (folded in precompute)
  #pragma unroll
  for (int p = 1; p < 8; p++) x_r += g_xpart[p * (NB * NH) + b * NH + t];

  float wpw1r[32];
  ull w2p[16];
  float csum = 0.f;
  #pragma unroll
  for (int k = 0; k < 32; k++) { wpw1r[k] = g_WpW1[k * NH + t]; csum += wpw1r[k]; }
  #pragma unroll
  for (int j = 0; j < 16; j++)
    w2p[j] = pack2(W2[(size_t)(wid * 32 + 2*j) * 32 + lane],
                   W2[(size_t)(wid * 32 + 2*j + 1) * 32 + lane]);
  float bpw1c = g_bpW1[t] - 0.001953125f * csum;
  float b2r = b2[lane];

  int khalf = wid >> 2;
  int lh = (wid & 3) * 8 + (lane >> 2);
  int lg = lane & 3;
  float blr = bl[lg * 32 + lh];
  float creg = 0.f, sumr = 0.f;
  float m0 = 1.0f, m1 = 1.0f;
  __syncthreads();

  const float* gumbase = g_gumbel + (size_t)b * (NSTEPS * NE) + 2 * t;

  // ======== 64-step loop ========
  for (int s = 0; s < NSTEPS; s++) {
    float2 gpair = *(const float2*)(gumbase + s * NE);
    float hpreg = s_h[lane];

    if (s > 0) {
      ull kk = s_key[0];
      #pragma unroll
      for (int i = 1; i < 8; i++) { ull o = s_key[i]; if (o > kk) kk = o; }
      int id = (int)(0xFFFFFFFFu - (unsigned)(kk & 0xFFFFFFFFull));
      if (id == 2 * t) m0 = 0.0f;
      if (id == 2 * t + 1) m1 = 0.0f;
      const float* kc = s_kpT + id;
      float xv0 = x_r + bpw1c, xv1 = 0.f, xv2 = 0.f, xv3 = 0.f;
      #pragma unroll
      for (int k = 0; k < 32; k += 4) {
        xv0 = fmaf(kc[(k + 0) * KPT_S], wpw1r[k + 0], xv0);
        xv1 = fmaf(kc[(k + 1) * KPT_S], wpw1r[k + 1], xv1);
        xv2 = fmaf(kc[(k + 2) * KPT_S], wpw1r[k + 2], xv2);
        xv3 = fmaf(kc[(k + 3) * KPT_S], wpw1r[k + 3], xv3);
      }
      x_r = (xv0 + xv1) + (xv2 + xv3);
      if (wid == 0) sumr += s_kpT[lane * KPT_S + id] - 0.001953125f;
      if (t == 0) out[OFF_UNITS + (size_t)b * NSTEPS + (s - 1)] = (float)id * sel;
    }
    float tval = fmaxf(func_r + x_r, 0.0f);
    s_t[t] = tval;
    __syncwarp();
    {
      const ull* tp = (const ull*)(s_t + wid * 32);
      ull za = 0ull, zb = 0ull;
      #pragma unroll
      for (int j = 0; j < 16; j += 2) {
        ffma2(za, tp[j], w2p[j]);
        ffma2(zb, tp[j + 1], w2p[j + 1]);
      }
      float2 zv = unpack2(fadd2(za, zb));
      s_zred[t] = zv.x + zv.y;
    }
    __syncthreads();

    float z2l;
    {
      float r0 = s_zred[lane]        + s_zred[32 + lane];
      float r1 = s_zred[64 + lane]   + s_zred[96 + lane];
      float r2 = s_zred[128 + lane]  + s_zred[160 + lane];
      float r3 = s_zred[192 + lane]  + s_zred[224 + lane];
      z2l = b2r + ((r0 + r1) + (r2 + r3));
    }
    {
      float accA = (khalf == 0) ? blr : 0.f, accB = 0.f;
      const float* wbase = s_Wxh + lh * 8 + lg * 2 + khalf * (16 * 258);
      #pragma unroll
      for (int k16 = 0; k16 < 16; k16 += 2) {
        int k = khalf * 16 + k16;
        float z2a = __shfl_sync(0xffffffffu, z2l, k);
        float ha  = __shfl_sync(0xffffffffu, hpreg, k);
        float2 wa = unpack2(*(const ull*)(wbase + k16 * 258));
        accA = fmaf(z2a, wa.x, fmaf(ha, wa.y, accA));
        float z2b = __shfl_sync(0xffffffffu, z2l, k + 1);
        float hb  = __shfl_sync(0xffffffffu, hpreg, k + 1);
        float2 wb = unpack2(*(const ull*)(wbase + (k16 + 1) * 258));
        accB = fmaf(z2b, wb.x, fmaf(hb, wb.y, accB));
      }
      float acc = accA + accB;
      if (khalf == 1) s_part[lh * 4 + lg] = acc;
      __syncthreads();
      if (khalf == 0) {
        acc += s_part[lh * 4 + lg];
        float e2 = __expf((lg == 2) ? (2.f * acc) : (-acc));
        float tg = (lg == 2) ? (1.f - __fdividef(2.f, e2 + 1.f))
                             : __fdividef(1.f, 1.f + e2);
        int base = lane & ~3;
        float iv = __shfl_sync(0xffffffffu, tg, base);
        float fv = __shfl_sync(0xffffffffu, tg, base + 1);
        float gv = __shfl_sync(0xffffffffu, tg, base + 2);
        float ov = __shfl_sync(0xffffffffu, tg, base + 3);
        creg = fv * creg + iv * gv;
        float e2c = __expf(2.f * creg);
        float hv = ov * (1.f - __fdividef(2.f, e2c + 1.f));
        if (lg == 0) { s_h[lh] = hv; s_hd[lh] = dup2(hv); }
      }
    }
    __syncthreads();

    ull a0 = 0ull, a1 = 0ull, a2 = 0ull, a3 = 0ull;
    {
      const float* kb = s_kpT + 2 * t;
      #pragma unroll
      for (int q = 0; q < 8; q++) {
        ffma2(a0, *(const ull*)(kb + (4*q + 0) * KPT_S), s_hd[4*q + 0]);
        ffma2(a1, *(const ull*)(kb + (4*q + 1) * KPT_S), s_hd[4*q + 1]);
        ffma2(a2, *(const ull*)(kb + (4*q + 2) * KPT_S), s_hd[4*q + 2]);
        ffma2(a3, *(const ull*)(kb + (4*q + 3) * KPT_S), s_hd[4*q + 3]);
      }
    }
    float2 yv = unpack2(fadd2(fadd2(a0, a1), fadd2(a2, a3)));
    float y0 = yv.x * m0, y1 = yv.y * m1;
    __stcs((float2*)(out + ((size_t)b * NSTEPS + s) * NE + 2 * t),
           make_float2(y0 * sel, y1 * sel));
    float p0 = __expf(y0), p1 = __expf(y1);
    float ssum = p0 + p1;
    #pragma unroll
    for (int o = 16; o; o >>= 1) ssum += __shfl_xor_sync(0xffffffffu, ssum, o);
    if (lane == 0) s_red[wid] = ssum;
    __syncthreads();

    float S;
    {
      float r0 = s_red[0] + s_red[1], r1 = s_red[2] + s_red[3];
      float r2 = s_red[4] + s_red[5], r3 = s_red[6] + s_red[7];
      S = (r0 + r1) + (r2 + r3);
    }
    float v0 = fmaf(S, gpair.x, p0);
    float v1 = fmaf(S, gpair.y, p1);
    ull kA = ((ull)fenc(v0) << 32) | (ull)(0xFFFFFFFFu - (unsigned)(2 * t));
    ull kB = ((ull)fenc(v1) << 32) | (ull)(0xFFFFFFFFu - (unsigned)(2 * t + 1));
    ull km = (kA > kB) ? kA : kB;
    #pragma unroll
    for (int o = 16; o; o >>= 1) {
      ull other = __shfl_xor_sync(0xffffffffu, km, o);
      if (other > km) km = other;
    }
    if (lane == 0) s_key[wid] = km;
    __syncthreads();
  }

  // ======== final selection ========
  {
    ull kk = s_key[0];
    #pragma unroll
    for (int i = 1; i < 8; i++) { ull o = s_key[i]; if (o > kk) kk = o; }
    int id = (int)(0xFFFFFFFFu - (unsigned)(kk & 0xFFFFFFFFull));
    if (wid == 0) sumr += s_kpT[lane * KPT_S + id] - 0.001953125f;
    if (t == 0) out[OFF_UNITS + (size_t)b * NSTEPS + (NSTEPS - 1)] = (float)id * sel;
  }
  if (wid == 0) s_sum[lane] = sumr;
  __syncthreads();

  // ======== epilogue ========
  for (int j = t; j < NAR; j += 256) {
    float acc0 = ar0[(size_t)b * NAR + j] + 64.0f * bp[j];
    float acc1 = 0.f, acc2 = 0.f, acc3 = 0.f;
    #pragma unroll
    for (int k = 0; k < 32; k += 4) {
      acc0 = fmaf(s_sum[k + 0], Wp[(size_t)(k + 0) * NAR + j], acc0);
      acc1 = fmaf(s_sum[k + 1], Wp[(size_t)(k + 1) * NAR + j], acc1);
      acc2 = fmaf(s_sum[k + 2], Wp[(size_t)(k + 2) * NAR + j], acc2);
      acc3 = fmaf(s_sum[k + 3], Wp[(size_t)(k + 3) * NAR + j], acc3);
    }
    __stcs(out + OFF_AR + (size_t)b * NAR + j, ((acc0 + acc1) + (acc2 + acc3)) * sel);
  }
}

// ---------------- host threefry ----------------
static inline void h_tf2x32(uint32_t k0, uint32_t k1, uint32_t x0, uint32_t x1,
                            uint32_t &o0, uint32_t &o1) {
  uint32_t ks2 = k0 ^ k1 ^ 0x1BD11BDAu;
  x0 += k0; x1 += k1;
#define HRND(r) { x0 += x1; x1 = (x1 << (r)) | (x1 >> (32 - (r))); x1 ^= x0; }
  HRND(13) HRND(15) HRND(26) HRND(6)   x0 += k1;  x1 += ks2 + 1u;
  HRND(17) HRND(29) HRND(16) HRND(24)  x0 += ks2; x1 += k0  + 2u;
  HRND(13) HRND(15) HRND(26) HRND(6)   x0 += k0;  x1 += k1  + 3u;
  HRND(17) HRND(29) HRND(16) HRND(24)  x0 += k1;  x1 += ks2 + 4u;
  HRND(13) HRND(15) HRND(26) HRND(6)   x0 += ks2; x1 += k0  + 5u;
#undef HRND
  o0 = x0; o1 = x1;
}

// ---------------- launcher ----------------
extern "C" void kernel_launch(void* const* d_in, const int* in_sizes, int n_in,
                              void* d_out, int out_size) {
  const float* ar_in   = (const float*)d_in[0];
  const int*   action  = (const int*)  d_in[1];
  const float* emb     = (const float*)d_in[2];
  const float* Wf      = (const float*)d_in[3];
  const float* bf      = (const float*)d_in[4];
  const float* Wk      = (const float*)d_in[5];
  const float* bk      = (const float*)d_in[6];
  const float* W1      = (const float*)d_in[7];
  const float* b1      = (const float*)d_in[8];
  const float* W2      = (const float*)d_in[9];
  const float* b2      = (const float*)d_in[10];
  const float* Wx      = (const float*)d_in[11];
  const float* Wh      = (const float*)d_in[12];
  const float* bl      = (const float*)d_in[13];
  const float* Wp      = (const float*)d_in[14];
  const float* bp      = (const float*)d_in[15];
  const float* table   = (const float*)d_in[16];
  const float* selt    = (const float*)d_in[17];
  float* out = (float*)d_out;

  SubKeys sk;
  {
    uint32_t k0 = 0u, k1 = 42u;
    for (int s = 0; s < NSTEPS; s++) {
      uint32_t n0, n1, s0, s1;
      h_tf2x32(k0, k1, 0u, 0u, n0, n1);
      h_tf2x32(k0, k1, 0u, 1u, s0, s1);
      sk.a[s] = s0; sk.b[s] = s1;
      k0 = n0; k1 = n1;
    }
  }

  cudaFuncSetAttribute(persist_kernel, cudaFuncAttributeMaxDynamicSharedMemorySize,
                       SMEM_FLOATS * (int)sizeof(float));

  // Fork: gumbel on a side stream, parallel with fused precompute-A; join before persist.
  static cudaStream_t side = nullptr;
  static cudaEvent_t evFork = nullptr, evJoin = nullptr;
  if (side == nullptr) {
    cudaStreamCreateWithFlags(&side, cudaStreamNonBlocking);
    cudaEventCreateWithFlags(&evFork, cudaEventDisableTiming);
    cudaEventCreateWithFlags(&evJoin, cudaEventDisableTiming);
  }

  cudaEventRecord(evFork, 0);
  cudaStreamWaitEvent(side, evFork, 0);

  gumbel_kernel<<<8192, 256, 0, side>>>(sk);
  precompute_kernel<<<KP_BLKS + GEMM_BLKS + WPW1_BLKS + 1 + FUNC_BLKS, 256>>>(
      Wp, bp, W1, ar_in, action, emb, Wk, bk, Wf, bf, table, b1);

  cudaEventRecord(evJoin, side);
  cudaStreamWaitEvent(0, evJoin, 0);

  persist_kernel<<<256, 256, SMEM_FLOATS * sizeof(float)>>>(
      ar_in, W2, b2, Wx, Wh, bl, Wp, bp, selt, out);
}